// round 8
// baseline (speedup 1.0000x reference)
#include <cuda_runtime.h>
#include <cuda_bf16.h>
#include <cstdint>

#define NV 100000
#define NE 300000
#define DH 128
#define LHID 12
#define NB_SCAN 98   // ceil(NV/1024)
#define NT64 1563    // ceil(NV/64) A-tiles

// ---------------- scratch (static device globals; no allocation allowed) ---
__device__ float g_Y[NV * DH];              // self-transform output (fp32), buf 0
__device__ float g_N[NV * DH];              // neighbor-transform output, buf 0
__device__ float g_Y2[NV * DH];             // ping-pong buf 1
__device__ float g_N2[NV * DH];
__device__ __nv_bfloat16 g_Ah[NV * DH];     // plane buffers (layer input / last out)
__device__ __nv_bfloat16 g_Al[NV * DH];
__device__ __nv_bfloat16 g_Rh[NV * DH];     // residual (layer-1 agg) hi
__device__ __nv_bfloat16 g_Rl[NV * DH];     // residual lo
__device__ __nv_bfloat16 g_WH[13 * 256 * DH];  // pre-split weights hi (W0|W1 per layer)
__device__ __nv_bfloat16 g_WL[13 * 256 * DH];  // pre-split weights lo
__device__ float g_NL[NV * 3];              // final-layer neighbor transform
// CSR build
__device__ int g_deg[NV];
__device__ int g_incl[NV];
__device__ int g_bsum[NB_SCAN];
__device__ int g_indptr[NV + 1];
__device__ int g_cursor[NV];
__device__ int g_adj[2 * NE];

// ======================= helpers ===========================================
__device__ __forceinline__ uint32_t smem_u32(const void* p) {
    uint32_t a;
    asm("{ .reg .u64 t; cvta.to.shared.u64 t, %1; cvt.u32.u64 %0, t; }"
        : "=r"(a) : "l"(p));
    return a;
}
__device__ __forceinline__ void ldmatrix_x4(uint32_t* r, uint32_t addr) {
    asm volatile("ldmatrix.sync.aligned.m8n8.x4.shared.b16 {%0,%1,%2,%3}, [%4];"
                 : "=r"(r[0]), "=r"(r[1]), "=r"(r[2]), "=r"(r[3]) : "r"(addr));
}
__device__ __forceinline__ void mma16816(float* c, const uint32_t* a, const uint32_t* b) {
    asm volatile(
        "mma.sync.aligned.m16n8k16.row.col.f32.bf16.bf16.f32 "
        "{%0,%1,%2,%3}, {%4,%5,%6,%7}, {%8,%9}, {%0,%1,%2,%3};"
        : "+f"(c[0]), "+f"(c[1]), "+f"(c[2]), "+f"(c[3])
        : "r"(a[0]), "r"(a[1]), "r"(a[2]), "r"(a[3]), "r"(b[0]), "r"(b[1]));
}
__device__ __forceinline__ uint32_t pk(__nv_bfloat16 a, __nv_bfloat16 b) {
    uint16_t ua = *(uint16_t*)&a, ub = *(uint16_t*)&b;
    return (uint32_t)ua | ((uint32_t)ub << 16);
}
__device__ __forceinline__ float2 up2(uint32_t p) {
    __nv_bfloat162 b = *reinterpret_cast<__nv_bfloat162*>(&p);
    return make_float2(__bfloat162float(b.x), __bfloat162float(b.y));
}
__device__ __forceinline__ void cp16(uint32_t dst, const void* src) {
    asm volatile("cp.async.cg.shared.global [%0], [%1], 16;"
                 :: "r"(dst), "l"(src));
}
__device__ __forceinline__ float4 ldcs4(const float4* p) {
    float4 v;
    asm volatile("ld.global.cs.v4.f32 {%0,%1,%2,%3}, [%4];"
                 : "=f"(v.x), "=f"(v.y), "=f"(v.z), "=f"(v.w) : "l"(p));
    return v;
}

// row acc -> relu -> hi/lo bf16 planes in smem
__device__ __forceinline__ void split_store(char* smem, uint32_t hi_off,
                                            uint32_t lo_off, float4 acc) {
    acc.x = fmaxf(acc.x, 0.f); acc.y = fmaxf(acc.y, 0.f);
    acc.z = fmaxf(acc.z, 0.f); acc.w = fmaxf(acc.w, 0.f);
    __nv_bfloat16 h0 = __float2bfloat16_rn(acc.x), h1 = __float2bfloat16_rn(acc.y);
    __nv_bfloat16 h2 = __float2bfloat16_rn(acc.z), h3 = __float2bfloat16_rn(acc.w);
    float l0 = acc.x - __bfloat162float(h0), l1 = acc.y - __bfloat162float(h1);
    float l2 = acc.z - __bfloat162float(h2), l3 = acc.w - __bfloat162float(h3);
    *(uint2*)(smem + hi_off) = make_uint2(pk(h0, h1), pk(h2, h3));
    *(uint2*)(smem + lo_off) =
        make_uint2(pk(__float2bfloat16_rn(l0), __float2bfloat16_rn(l1)),
                   pk(__float2bfloat16_rn(l2), __float2bfloat16_rn(l3)));
}

// gather one row: acc = Y[row] + sum N[adj], 4-way batched
__device__ __forceinline__ float4 gather_row(const float4* __restrict__ Y,
                                             const float4* __restrict__ Nb,
                                             const int* __restrict__ indptr,
                                             const int* __restrict__ adj,
                                             int row, int lane) {
    float4 acc = ldcs4(Y + (size_t)row * 32 + lane);
    const int s = indptr[row], e = indptr[row + 1];
    int k = s;
    for (; k + 4 <= e; k += 4) {
        int j0 = __ldg(adj + k), j1 = __ldg(adj + k + 1);
        int j2 = __ldg(adj + k + 2), j3 = __ldg(adj + k + 3);
        float4 n0 = Nb[(size_t)j0 * 32 + lane];
        float4 n1 = Nb[(size_t)j1 * 32 + lane];
        float4 n2 = Nb[(size_t)j2 * 32 + lane];
        float4 n3 = Nb[(size_t)j3 * 32 + lane];
        acc.x += (n0.x + n1.x) + (n2.x + n3.x);
        acc.y += (n0.y + n1.y) + (n2.y + n3.y);
        acc.z += (n0.z + n1.z) + (n2.z + n3.z);
        acc.w += (n0.w + n1.w) + (n2.w + n3.w);
    }
    if (k + 2 <= e) {
        int j0 = __ldg(adj + k), j1 = __ldg(adj + k + 1);
        float4 n0 = Nb[(size_t)j0 * 32 + lane];
        float4 n1 = Nb[(size_t)j1 * 32 + lane];
        acc.x += n0.x + n1.x; acc.y += n0.y + n1.y;
        acc.z += n0.z + n1.z; acc.w += n0.w + n1.w;
        k += 2;
    }
    if (k < e) {
        int j0 = __ldg(adj + k);
        float4 n0 = Nb[(size_t)j0 * 32 + lane];
        acc.x += n0.x; acc.y += n0.y; acc.z += n0.z; acc.w += n0.w;
    }
    return acc;
}

// SMEM layout (bytes). Row stride 272 = 17*16B -> conflict-free ldmatrix.
#define TSTR 272
#define OFF_BIAS 0
#define OFF_A0   1024
#define A_PLANE  17408                      // 64*272 per plane
#define A_BUF    34816                      // hi+lo
#define OFF_A1   (OFF_A0 + A_BUF)           // 35840
#define OFF_BH   (OFF_A1 + A_BUF)           // 70656
#define OFF_BL   (OFF_BH + 256 * TSTR)      // 140288
#define SMEM_TOTAL (OFF_BL + 256 * TSTR)    // 209920

// =================== consumer (MMA) body, shared by both kernels ===========
struct MmaCtx {
    uint32_t a_roff, b_base;
    int wm, wn, g, tq;
    float* dbase;
    const float* bs;
    bool isY;
};

__device__ __forceinline__ void mma_tile(const MmaCtx& C, uint32_t a_base,
                                         int m0, float* Yout, float* Nbuf) {
    float acc[2][8][4];
#pragma unroll
    for (int mt = 0; mt < 2; mt++)
#pragma unroll
        for (int nt = 0; nt < 8; nt++)
#pragma unroll
            for (int q = 0; q < 4; q++) acc[mt][nt][q] = 0.f;

#pragma unroll
    for (int s = 0; s < 8; s++) {
        uint32_t Ahf[2][4], Alf[2][4], Bhf[4][4], Blf[4][4];
#pragma unroll
        for (int mt = 0; mt < 2; mt++) {
            uint32_t ad = a_base + (uint32_t)(mt * 16 * TSTR + s * 32);
            ldmatrix_x4(Ahf[mt], ad);
            ldmatrix_x4(Alf[mt], ad + A_PLANE);
        }
#pragma unroll
        for (int q = 0; q < 4; q++) {
            uint32_t bd = C.b_base + (uint32_t)(q * 16 * TSTR + s * 32);
            ldmatrix_x4(Bhf[q], bd);
            ldmatrix_x4(Blf[q], bd + (OFF_BL - OFF_BH));
        }
#pragma unroll
        for (int mt = 0; mt < 2; mt++)
#pragma unroll
            for (int nt = 0; nt < 8; nt++) {
                const uint32_t* bh = &Bhf[nt >> 1][(nt & 1) * 2];
                const uint32_t* bl = &Blf[nt >> 1][(nt & 1) * 2];
                mma16816(acc[mt][nt], Ahf[mt], bh);
                mma16816(acc[mt][nt], Alf[mt], bh);
                mma16816(acc[mt][nt], Ahf[mt], bl);
            }
    }
#pragma unroll
    for (int mt = 0; mt < 2; mt++) {
        int row0 = m0 + C.wm * 32 + mt * 16 + C.g;
#pragma unroll
        for (int nt = 0; nt < 8; nt++) {
            int col = C.wn * 64 + nt * 8 + C.tq * 2;
            float b0v = C.bs[col], b1v = C.bs[col + 1];
            int cc = C.isY ? col : (col - 128);
            if (row0 < NV) {
                float2 o = make_float2(acc[mt][nt][0] + b0v, acc[mt][nt][1] + b1v);
                *(float2*)(C.dbase + (size_t)row0 * 128 + cc) = o;
            }
            if (row0 + 8 < NV) {
                float2 o = make_float2(acc[mt][nt][2] + b0v, acc[mt][nt][3] + b1v);
                *(float2*)(C.dbase + (size_t)(row0 + 8) * 128 + cc) = o;
            }
        }
    }
}

// ---------------------------------------------------------------------------
// Persistent, pipelined plane-input dual GEMM (layers 1 and 2).
// 256 threads, 8 warps MMA, double-buffered cp.async A prefetch.
// ---------------------------------------------------------------------------
__global__ __launch_bounds__(256, 1)
void gemm_dual_tc(const __nv_bfloat16* __restrict__ XH,
                  const __nv_bfloat16* __restrict__ XL,
                  const __nv_bfloat16* __restrict__ WH,
                  const __nv_bfloat16* __restrict__ WL,
                  const float* __restrict__ b0, const float* __restrict__ b1,
                  float* __restrict__ Yout, float* __restrict__ Nbuf)
{
    extern __shared__ char smem[];
    const uint32_t sb = smem_u32(smem);
    const int tid  = threadIdx.x;
    const int wid  = tid >> 5;
    const int lane = tid & 31;

    ((float*)(smem + OFF_BIAS))[tid] = (tid < 128) ? b0[tid] : b1[tid - 128];

#pragma unroll
    for (int i = 0; i < 16; i++) {
        int c = tid + i * 256;
        int n = c >> 4, kc = c & 15;
        uint32_t so = (uint32_t)(n * TSTR + kc * 16);
        const size_t go = ((size_t)n << 7) + kc * 8;
        cp16(sb + OFF_BH + so, WH + go);
        cp16(sb + OFF_BL + so, WL + go);
    }

    auto issueA = [&](int t, int buf) {
        const uint32_t abase = sb + (buf ? OFF_A1 : OFF_A0);
        char* abasep = smem + (buf ? OFF_A1 : OFF_A0);
        const int m0 = t * 64;
#pragma unroll
        for (int i = 0; i < 4; i++) {
            int c = tid + i * 256;
            int r = c >> 4, kc = c & 15;
            int grow = m0 + r;
            uint32_t so = (uint32_t)(r * TSTR + kc * 16);
            if (grow < NV) {
                const size_t go = ((size_t)grow << 7) + kc * 8;
                cp16(abase + so, XH + go);
                cp16(abase + A_PLANE + so, XL + go);
            } else {
                *(uint4*)(abasep + so) = make_uint4(0, 0, 0, 0);
                *(uint4*)(abasep + A_PLANE + so) = make_uint4(0, 0, 0, 0);
            }
        }
    };

    int t = blockIdx.x;
    if (t >= NT64) return;
    issueA(t, 0);
    asm volatile("cp.async.commit_group;");

    MmaCtx C;
    C.wm = wid & 1; C.wn = wid >> 1;
    C.a_roff = (uint32_t)((C.wm * 32 + (lane & 15)) * TSTR + ((lane >> 4) * 8) * 2);
    C.b_base = sb + OFF_BH +
               (uint32_t)((C.wn * 64 + (lane & 7) + ((lane >> 4) * 8)) * TSTR +
                          (((lane >> 3) & 1) * 8) * 2);
    C.g = lane >> 2; C.tq = lane & 3;
    C.isY = (C.wn < 2);
    C.dbase = C.isY ? Yout : Nbuf;
    C.bs = (const float*)(smem + OFF_BIAS);

    int p = 0;
    while (t < NT64) {
        const int tn = t + gridDim.x;
        if (tn < NT64) {
            issueA(tn, p ^ 1);
            asm volatile("cp.async.commit_group;");
            asm volatile("cp.async.wait_group 1;");
        } else {
            asm volatile("cp.async.wait_group 0;");
        }
        __syncthreads();
        mma_tile(C, sb + (p ? OFF_A1 : OFF_A0) + C.a_roff, t * 64, Yout, Nbuf);
        __syncthreads();
        t = tn;
        p ^= 1;
    }
}

// ---------------------------------------------------------------------------
// FUSED persistent GEMM: producer warps (8..11) gather relu(Y+sum N) for the
// NEXT tile into the smem ring (hi/lo split in regs); consumer warps (0..7)
// run the MMA pipeline on the current tile. One __syncthreads per tile.
// ---------------------------------------------------------------------------
__global__ __launch_bounds__(384, 1)
void gemm_fused_tc(const float4* __restrict__ Yprev, const float4* __restrict__ Nprev,
                   const int* __restrict__ indptr, const int* __restrict__ adj,
                   const __nv_bfloat16* __restrict__ WH,
                   const __nv_bfloat16* __restrict__ WL,
                   const float* __restrict__ b0, const float* __restrict__ b1,
                   float* __restrict__ Yout, float* __restrict__ Nbuf)
{
    extern __shared__ char smem[];
    const uint32_t sb = smem_u32(smem);
    const int tid  = threadIdx.x;
    const int wid  = tid >> 5;
    const int lane = tid & 31;
    const bool isProd = (wid >= 8);

    if (tid < 256)
        ((float*)(smem + OFF_BIAS))[tid] = (tid < 128) ? b0[tid] : b1[tid - 128];

    // B tiles: 256 rows x 16 chunks x 2 planes, all 384 threads
    for (int i = tid; i < 4096; i += 384) {
        int n = i >> 4, kc = i & 15;
        uint32_t so = (uint32_t)(n * TSTR + kc * 16);
        const size_t go = ((size_t)n << 7) + kc * 8;
        cp16(sb + OFF_BH + so, WH + go);
        cp16(sb + OFF_BL + so, WL + go);
    }
    asm volatile("cp.async.commit_group;");

    // producer: 4 warps x 16 rows each
    auto produce = [&](int t, int buf) {
        const int wp = wid - 8;
        char* base = smem + (buf ? OFF_A1 : OFF_A0);
#pragma unroll 1
        for (int rr = 0; rr < 16; rr++) {
            int r = wp * 16 + rr;
            int grow = t * 64 + r;
            uint32_t so = (uint32_t)(r * TSTR + lane * 8);
            if (grow < NV) {
                float4 acc = gather_row(Yprev, Nprev, indptr, adj, grow, lane);
                split_store(base, so, so + A_PLANE, acc);
            } else {
                *(uint2*)(base + so) = make_uint2(0, 0);
                *(uint2*)(base + so + A_PLANE) = make_uint2(0, 0);
            }
        }
    };

    int t = blockIdx.x;
    if (t >= NT64) return;
    if (isProd) produce(t, 0);
    asm volatile("cp.async.wait_group 0;");
    __syncthreads();

    MmaCtx C;
    C.wm = wid & 1; C.wn = wid >> 1;
    C.a_roff = (uint32_t)((C.wm * 32 + (lane & 15)) * TSTR + ((lane >> 4) * 8) * 2);
    C.b_base = sb + OFF_BH +
               (uint32_t)(((C.wn & 3) * 64 + (lane & 7) + ((lane >> 4) * 8)) * TSTR +
                          (((lane >> 3) & 1) * 8) * 2);
    C.g = lane >> 2; C.tq = lane & 3;
    C.isY = (C.wn < 2);
    C.dbase = C.isY ? Yout : Nbuf;
    C.bs = (const float*)(smem + OFF_BIAS);

    int p = 0;
    while (t < NT64) {
        const int tn = t + gridDim.x;
        if (isProd) {
            if (tn < NT64) produce(tn, p ^ 1);
        } else {
            mma_tile(C, sb + (p ? OFF_A1 : OFF_A0) + C.a_roff, t * 64, Yout, Nbuf);
        }
        __syncthreads();
        t = tn;
        p ^= 1;
    }
}

// ---------------------------------------------------------------------------
// CSR build kernels (edges are static; built once per launch)
// ---------------------------------------------------------------------------
__global__ __launch_bounds__(256)
void deg_count(const int2* __restrict__ edges, int* __restrict__ deg)
{
    int t = blockIdx.x * blockDim.x + threadIdx.x;
    if (t >= NE) return;
    int2 e = edges[t];
    atomicAdd(&deg[e.x], 1);
    atomicAdd(&deg[e.y], 1);
}

__global__ __launch_bounds__(1024)
void scan1(const int* __restrict__ deg, int* __restrict__ incl, int* __restrict__ bsum)
{
    __shared__ int ws[32];
    int i = blockIdx.x * 1024 + threadIdx.x;
    int lane = threadIdx.x & 31, wid = threadIdx.x >> 5;
    int x = (i < NV) ? deg[i] : 0;
#pragma unroll
    for (int d = 1; d < 32; d <<= 1) {
        int t = __shfl_up_sync(0xffffffffu, x, d);
        if (lane >= d) x += t;
    }
    if (lane == 31) ws[wid] = x;
    __syncthreads();
    if (wid == 0) {
        int w = ws[lane];
#pragma unroll
        for (int d = 1; d < 32; d <<= 1) {
            int t = __shfl_up_sync(0xffffffffu, w, d);
            if (lane >= d) w += t;
        }
        ws[lane] = w;
    }
    __syncthreads();
    int off = (wid > 0) ? ws[wid - 1] : 0;
    int v = x + off;
    if (i < NV) incl[i] = v;
    if (threadIdx.x == 1023) bsum[blockIdx.x] = v;
}

__global__ void scan2(int* bsum)
{
    if (threadIdx.x == 0 && blockIdx.x == 0) {
        int acc = 0;
        for (int b = 0; b < NB_SCAN; b++) { int t = bsum[b]; bsum[b] = acc; acc += t; }
    }
}

__global__ __launch_bounds__(256)
void scan3(const int* __restrict__ incl, const int* __restrict__ deg,
           const int* __restrict__ bsum, int* __restrict__ indptr,
           int* __restrict__ cursor)
{
    int i = blockIdx.x * blockDim.x + threadIdx.x;
    if (i >= NV) return;
    int total = incl[i] + bsum[i >> 10];
    int ex = total - deg[i];
    indptr[i] = ex;
    cursor[i] = ex;
    if (i == NV - 1) indptr[NV] = total;
}

__global__ __launch_bounds__(256)
void fill_adj(const int2* __restrict__ edges, int* __restrict__ cursor,
              int* __restrict__ adj)
{
    int t = blockIdx.x * blockDim.x + threadIdx.x;
    if (t >= NE) return;
    int2 e = edges[t];
    int p = atomicAdd(&cursor[e.x], 1); adj[p] = e.y;
    int q = atomicAdd(&cursor[e.y], 1); adj[q] = e.x;
}

// ---------------------------------------------------------------------------
// Weight pre-split: all 13 layers' (W0|W1) fp32 -> bf16 hi/lo planes
// ---------------------------------------------------------------------------
__global__ __launch_bounds__(256)
void wsplit(const float* __restrict__ W0_1, const float* __restrict__ W1_1,
            const float* __restrict__ W0_h, const float* __restrict__ W1_h,
            __nv_bfloat16* __restrict__ WH, __nv_bfloat16* __restrict__ WL)
{
    int idx = blockIdx.x * blockDim.x + threadIdx.x;   // float4 units
    if (idx >= 13 * 256 * 32) return;
    int layer = idx / (256 * 32);
    int rem   = idx % (256 * 32);
    int row   = rem >> 5;
    int c4    = (rem & 31) * 4;
    const float* src;
    if (layer == 0)
        src = (row < 128) ? (W0_1 + (size_t)row * 128) : (W1_1 + (size_t)(row - 128) * 128);
    else
        src = (row < 128) ? (W0_h + (size_t)(layer - 1) * 16384 + (size_t)row * 128)
                          : (W1_h + (size_t)(layer - 1) * 16384 + (size_t)(row - 128) * 128);
    float4 v = *(const float4*)(src + c4);
    __nv_bfloat16 h0 = __float2bfloat16_rn(v.x), h1 = __float2bfloat16_rn(v.y);
    __nv_bfloat16 h2 = __float2bfloat16_rn(v.z), h3 = __float2bfloat16_rn(v.w);
    float l0 = v.x - __bfloat162float(h0), l1 = v.y - __bfloat162float(h1);
    float l2 = v.z - __bfloat162float(h2), l3 = v.w - __bfloat162float(h3);
    size_t o = ((size_t)(layer * 256 + row) << 7) + c4;
    *(uint2*)(WH + o) = make_uint2(pk(h0, h1), pk(h2, h3));
    *(uint2*)(WL + o) = make_uint2(pk(__float2bfloat16_rn(l0), __float2bfloat16_rn(l1)),
                                   pk(__float2bfloat16_rn(l2), __float2bfloat16_rn(l3)));
}

// features fp32 -> hi/lo planes (no relu)
__global__ __launch_bounds__(256)
void featsplit(const float4* __restrict__ X, __nv_bfloat16* __restrict__ AH,
               __nv_bfloat16* __restrict__ AL)
{
    int idx = blockIdx.x * blockDim.x + threadIdx.x;   // float4 units
    if (idx >= NV * 32) return;
    float4 v = X[idx];
    __nv_bfloat16 h0 = __float2bfloat16_rn(v.x), h1 = __float2bfloat16_rn(v.y);
    __nv_bfloat16 h2 = __float2bfloat16_rn(v.z), h3 = __float2bfloat16_rn(v.w);
    float l0 = v.x - __bfloat162float(h0), l1 = v.y - __bfloat162float(h1);
    float l2 = v.z - __bfloat162float(h2), l3 = v.w - __bfloat162float(h3);
    *(uint2*)(AH + (size_t)idx * 4) = make_uint2(pk(h0, h1), pk(h2, h3));
    *(uint2*)(AL + (size_t)idx * 4) =
        make_uint2(pk(__float2bfloat16_rn(l0), __float2bfloat16_rn(l1)),
                   pk(__float2bfloat16_rn(l2), __float2bfloat16_rn(l3)));
}

// ---------------------------------------------------------------------------
// CSR gather-aggregate -> hi/lo planes (used after layer 1 and last layer)
// ---------------------------------------------------------------------------
__global__ __launch_bounds__(256)
void agg_csr(const float4* __restrict__ Y, const float4* __restrict__ Nb,
             const int* __restrict__ indptr, const int* __restrict__ adj,
             __nv_bfloat16* __restrict__ AH, __nv_bfloat16* __restrict__ AL)
{
    int w = (blockIdx.x * blockDim.x + threadIdx.x) >> 5;
    int lane = threadIdx.x & 31;
    if (w >= NV) return;
    float4 acc = gather_row(Y, Nb, indptr, adj, w, lane);
    acc.x = fmaxf(acc.x, 0.f); acc.y = fmaxf(acc.y, 0.f);
    acc.z = fmaxf(acc.z, 0.f); acc.w = fmaxf(acc.w, 0.f);
    __nv_bfloat16 h0 = __float2bfloat16_rn(acc.x), h1 = __float2bfloat16_rn(acc.y);
    __nv_bfloat16 h2 = __float2bfloat16_rn(acc.z), h3 = __float2bfloat16_rn(acc.w);
    float l0 = acc.x - __bfloat162float(h0), l1 = acc.y - __bfloat162float(h1);
    float l2 = acc.z - __bfloat162float(h2), l3 = acc.w - __bfloat162float(h3);
    size_t o = ((size_t)w << 7) + lane * 4;
    *(uint2*)(AH + o) = make_uint2(pk(h0, h1), pk(h2, h3));
    *(uint2*)(AL + o) = make_uint2(pk(__float2bfloat16_rn(l0), __float2bfloat16_rn(l1)),
                                   pk(__float2bfloat16_rn(l2), __float2bfloat16_rn(l3)));
}

// ---------------------------------------------------------------------------
// Final layer (+ fused aux emit)
// ---------------------------------------------------------------------------
__global__ __launch_bounds__(256)
void final_gemm(const __nv_bfloat16* __restrict__ Rh, const __nv_bfloat16* __restrict__ Rl,
                const __nv_bfloat16* __restrict__ Ahp, const __nv_bfloat16* __restrict__ Alp,
                const float* __restrict__ W0, const float* __restrict__ b0,
                const float* __restrict__ W1, const float* __restrict__ b1,
                float* __restrict__ Yout /*NV*3*/, float* __restrict__ Nl /*NV*3*/,
                float* __restrict__ Aux /*NV*128*/)
{
    __shared__ float w[6][128];
    int tid = threadIdx.x;
    for (int i = tid; i < 384; i += blockDim.x) {
        w[i / 128][i % 128]     = W0[i];
        w[3 + i / 128][i % 128] = W1[i];
    }
    __syncthreads();

    int row  = blockIdx.x * (blockDim.x >> 5) + (tid >> 5);
    int lane = tid & 31;
    if (row >= NV) return;

    size_t o = ((size_t)row << 7) + lane * 4;
    uint2 rh = *(const uint2*)(Rh + o), rl = *(const uint2*)(Rl + o);
    uint2 ah = *(const uint2*)(Ahp + o), al = *(const uint2*)(Alp + o);
    float2 a0 = up2(rh.x), a1 = up2(rh.y), b0f = up2(rl.x), b1f = up2(rl.y);
    float2 c0 = up2(ah.x), c1 = up2(ah.y), d0 = up2(al.x), d1 = up2(al.y);
    float4 ax = make_float4(c0.x + d0.x, c0.y + d0.y, c1.x + d1.x, c1.y + d1.y);
    *(float4*)(Aux + o) = ax;
    float4 z;
    z.x = (a0.x + b0f.x) + ax.x;
    z.y = (a0.y + b0f.y) + ax.y;
    z.z = (a1.x + b1f.x) + ax.z;
    z.w = (a1.y + b1f.y) + ax.w;

    float s[6];
#pragma unroll
    for (int oo = 0; oo < 6; oo++) {
        float4 wv = ((const float4*)w[oo])[lane];
        s[oo] = z.x * wv.x + z.y * wv.y + z.z * wv.z + z.w * wv.w;
    }
#pragma unroll
    for (int off = 16; off > 0; off >>= 1)
#pragma unroll
        for (int oo = 0; oo < 6; oo++)
            s[oo] += __shfl_down_sync(0xffffffffu, s[oo], off);

    if (lane == 0) {
#pragma unroll
        for (int oo = 0; oo < 3; oo++) {
            Yout[(size_t)row * 3 + oo] = s[oo] + b0[oo];
            Nl[(size_t)row * 3 + oo]   = s[3 + oo] + b1[oo];
        }
    }
}

// Final scatter over D_OUT=3
__global__ __launch_bounds__(256)
void scatter3(const float* __restrict__ Nl, const int2* __restrict__ edges,
              float* __restrict__ Out)
{
    int t = blockIdx.x * blockDim.x + threadIdx.x;
    if (t >= NE) return;
    int2 e = edges[t];
#pragma unroll
    for (int o = 0; o < 3; o++) {
        atomicAdd(Out + (size_t)e.x * 3 + o, Nl[(size_t)e.y * 3 + o]);
        atomicAdd(Out + (size_t)e.y * 3 + o, Nl[(size_t)e.x * 3 + o]);
    }
}

// ---------------------------------------------------------------------------
extern "C" void kernel_launch(void* const* d_in, const int* in_sizes, int n_in,
                              void* d_out, int out_size)
{
    const float* features = (const float*)d_in[0];
    const int2*  edges    = (const int2*)d_in[1];
    const float* W0_1 = (const float*)d_in[2];
    const float* b0_1 = (const float*)d_in[3];
    const float* W1_1 = (const float*)d_in[4];
    const float* b1_1 = (const float*)d_in[5];
    const float* W0_h = (const float*)d_in[6];
    const float* b0_h = (const float*)d_in[7];
    const float* W1_h = (const float*)d_in[8];
    const float* b1_h = (const float*)d_in[9];
    const float* W0_l = (const float*)d_in[10];
    const float* b0_l = (const float*)d_in[11];
    const float* W1_l = (const float*)d_in[12];
    const float* b1_l = (const float*)d_in[13];
    float* out = (float*)d_out;   // [vertices NV*3 | auxiliary NV*128]

    float *Y, *N, *Y2, *N2, *NL;
    __nv_bfloat16 *Ah, *Al, *Rh, *Rl, *WH, *WL;
    int *deg, *incl, *bsum, *indptr, *cursor, *adj;
    cudaGetSymbolAddress((void**)&Y,  g_Y);
    cudaGetSymbolAddress((void**)&N,  g_N);
    cudaGetSymbolAddress((void**)&Y2, g_Y2);
    cudaGetSymbolAddress((void**)&N2, g_N2);
    cudaGetSymbolAddress((void**)&NL, g_NL);
    cudaGetSymbolAddress((void**)&Ah, g_Ah);
    cudaGetSymbolAddress((void**)&Al, g_Al);
    cudaGetSymbolAddress((void**)&Rh, g_Rh);
    cudaGetSymbolAddress((void**)&Rl, g_Rl);
    cudaGetSymbolAddress((void**)&WH, g_WH);
    cudaGetSymbolAddress((void**)&WL, g_WL);
    cudaGetSymbolAddress((void**)&deg,    g_deg);
    cudaGetSymbolAddress((void**)&incl,   g_incl);
    cudaGetSymbolAddress((void**)&bsum,   g_bsum);
    cudaGetSymbolAddress((void**)&indptr, g_indptr);
    cudaGetSymbolAddress((void**)&cursor, g_cursor);
    cudaGetSymbolAddress((void**)&adj,    g_adj);

    cudaFuncSetAttribute(gemm_dual_tc,
                         cudaFuncAttributeMaxDynamicSharedMemorySize, SMEM_TOTAL);
    cudaFuncSetAttribute(gemm_fused_tc,
                         cudaFuncAttributeMaxDynamicSharedMemorySize, SMEM_TOTAL);

    int dev = 0, sms = 148;
    cudaGetDevice(&dev);
    cudaDeviceGetAttribute(&sms, cudaDevAttrMultiProcessorCount, dev);
    const int gemmBlocks = (sms < NT64) ? sms : NT64;   // persistent: 1 CTA/SM
    const int aggBlocks  = (NV * 32 + 255) / 256;
    const int edgeBlocks = (NE + 255) / 256;

    // ---- CSR build ----
    cudaMemsetAsync(deg, 0, NV * sizeof(int));
    deg_count<<<edgeBlocks, 256>>>(edges, deg);
    scan1<<<NB_SCAN, 1024>>>(deg, incl, bsum);
    scan2<<<1, 32>>>(bsum);
    scan3<<<(NV + 255) / 256, 256>>>(incl, deg, bsum, indptr, cursor);
    fill_adj<<<edgeBlocks, 256>>>(edges, cursor, adj);

    // ---- one-time conversions ----
    wsplit<<<(13 * 256 * 32 + 255) / 256, 256>>>(W0_1, W1_1, W0_h, W1_h, WH, WL);
    featsplit<<<(NV * 32 + 255) / 256, 256>>>((const float4*)features, Ah, Al);

    // ---- layer 1 (in -> hidden) ----
    gemm_dual_tc<<<gemmBlocks, 256, SMEM_TOTAL>>>(Ah, Al, WH, WL, b0_1, b1_1, Y, N);
    agg_csr<<<aggBlocks, 256>>>((const float4*)Y, (const float4*)N, indptr, adj, Rh, Rl);

    // ---- hidden layer 0: plane-input GEMM from residual planes ----
    gemm_dual_tc<<<gemmBlocks, 256, SMEM_TOTAL>>>(
        Rh, Rl, WH + (size_t)1 * 256 * 128, WL + (size_t)1 * 256 * 128,
        b0_h, b1_h, Y2, N2);

    // ---- hidden layers 1..11: fused gather+GEMM, ping-pong ----
    float* Yp = Y2; float* Np = N2;
    float* Yc = Y;  float* Nc = N;
    for (int l = 1; l < LHID; l++) {
        gemm_fused_tc<<<gemmBlocks, 384, SMEM_TOTAL>>>(
            (const float4*)Yp, (const float4*)Np, indptr, adj,
            WH + (size_t)(1 + l) * 256 * 128, WL + (size_t)(1 + l) * 256 * 128,
            b0_h + l * DH, b1_h + l * DH, Yc, Nc);
        float* ty = Yp; Yp = Yc; Yc = ty;
        float* tn = Np; Np = Nc; Nc = tn;
    }
    // last hidden output now in (Yp, Np)
    agg_csr<<<aggBlocks, 256>>>((const float4*)Yp, (const float4*)Np, indptr, adj, Ah, Al);

    // ---- final layer (+aux) ----
    final_gemm<<<(NV + 7) / 8, 256>>>(Rh, Rl, Ah, Al, W0_l, b0_l, W1_l, b1_l,
                                      out, NL, out + (size_t)NV * 3);
    scatter3<<<edgeBlocks, 256>>>(NL, edges, out);
}

// round 10
// speedup vs baseline: 2.6935x; 2.6935x over previous
#include <cuda_runtime.h>
#include <cuda_bf16.h>
#include <cstdint>

#define NV 100000
#define NE 300000
#define DH 128
#define LHID 12
#define NB_SCAN 98   // ceil(NV/1024)
#define NT64 1563    // ceil(NV/64) A-tiles

// ---------------- scratch (static device globals; no allocation allowed) ---
__device__ float g_Y[NV * DH];              // self-transform output (fp32)
__device__ float g_N[NV * DH];              // neighbor-transform output (fp32)
__device__ __nv_bfloat16 g_Ah[NV * DH];     // current layer input, hi plane
__device__ __nv_bfloat16 g_Al[NV * DH];     // current layer input, lo plane
__device__ __nv_bfloat16 g_Rh[NV * DH];     // residual (layer-1 agg) hi
__device__ __nv_bfloat16 g_Rl[NV * DH];     // residual lo
__device__ __nv_bfloat16 g_WH[13 * 256 * DH];  // pre-split weights hi (W0|W1 per layer)
__device__ __nv_bfloat16 g_WL[13 * 256 * DH];  // pre-split weights lo
__device__ float g_NL[NV * 3];              // final-layer neighbor transform
// CSR build
__device__ int g_deg[NV];
__device__ int g_incl[NV];
__device__ int g_bsum[NB_SCAN];
__device__ int g_indptr[NV + 1];
__device__ int g_cursor[NV];
__device__ int g_adj[2 * NE];

// ======================= helpers ===========================================
__device__ __forceinline__ uint32_t smem_u32(const void* p) {
    uint32_t a;
    asm("{ .reg .u64 t; cvta.to.shared.u64 t, %1; cvt.u32.u64 %0, t; }"
        : "=r"(a) : "l"(p));
    return a;
}
__device__ __forceinline__ void ldmatrix_x4(uint32_t* r, uint32_t addr) {
    asm volatile("ldmatrix.sync.aligned.m8n8.x4.shared.b16 {%0,%1,%2,%3}, [%4];"
                 : "=r"(r[0]), "=r"(r[1]), "=r"(r[2]), "=r"(r[3]) : "r"(addr));
}
__device__ __forceinline__ void mma16816(float* c, const uint32_t* a, const uint32_t* b) {
    asm volatile(
        "mma.sync.aligned.m16n8k16.row.col.f32.bf16.bf16.f32 "
        "{%0,%1,%2,%3}, {%4,%5,%6,%7}, {%8,%9}, {%0,%1,%2,%3};"
        : "+f"(c[0]), "+f"(c[1]), "+f"(c[2]), "+f"(c[3])
        : "r"(a[0]), "r"(a[1]), "r"(a[2]), "r"(a[3]), "r"(b[0]), "r"(b[1]));
}
__device__ __forceinline__ uint32_t pk(__nv_bfloat16 a, __nv_bfloat16 b) {
    uint16_t ua = *(uint16_t*)&a, ub = *(uint16_t*)&b;
    return (uint32_t)ua | ((uint32_t)ub << 16);
}
__device__ __forceinline__ float2 up2(uint32_t p) {
    __nv_bfloat162 b = *reinterpret_cast<__nv_bfloat162*>(&p);
    return make_float2(__bfloat162float(b.x), __bfloat162float(b.y));
}
__device__ __forceinline__ void cp16(uint32_t dst, const void* src) {
    asm volatile("cp.async.cg.shared.global [%0], [%1], 16;"
                 :: "r"(dst), "l"(src));
}
__device__ __forceinline__ float4 ldcs4(const float4* p) {
    float4 v;
    asm volatile("ld.global.cs.v4.f32 {%0,%1,%2,%3}, [%4];"
                 : "=f"(v.x), "=f"(v.y), "=f"(v.z), "=f"(v.w) : "l"(p));
    return v;
}

// SMEM layout (bytes). Row stride 272 = 17*16B -> conflict-free ldmatrix.
#define TSTR 272
#define OFF_BIAS 0
#define OFF_A0   1024
#define A_PLANE  17408                      // 64*272 per plane
#define A_BUF    34816                      // hi+lo
#define OFF_A1   (OFF_A0 + A_BUF)           // 35840
#define OFF_BH   (OFF_A1 + A_BUF)           // 70656
#define OFF_BL   (OFF_BH + 256 * TSTR)      // 140288
#define SMEM_TOTAL (OFF_BL + 256 * TSTR)    // 209920

// =================== consumer (MMA) body ===================================
struct MmaCtx {
    uint32_t a_roff, b_base;
    int wm, wn, g, tq;
    float* dbase;
    const float* bs;
    bool isY;
};

// software-pipelined fragment loads: prefetch k-step s+1 while computing s
__device__ __forceinline__ void mma_tile(const MmaCtx& C, uint32_t a_base,
                                         int m0, float* Yout, float* Nbuf) {
    float acc[2][8][4];
#pragma unroll
    for (int mt = 0; mt < 2; mt++)
#pragma unroll
        for (int nt = 0; nt < 8; nt++)
#pragma unroll
            for (int q = 0; q < 4; q++) acc[mt][nt][q] = 0.f;

    uint32_t Ahf[2][2][4], Alf[2][2][4], Bhf[2][4][4], Blf[2][4][4];

    auto loadfrag = [&](int s, int slot) {
#pragma unroll
        for (int mt = 0; mt < 2; mt++) {
            uint32_t ad = a_base + (uint32_t)(mt * 16 * TSTR + s * 32);
            ldmatrix_x4(Ahf[slot][mt], ad);
            ldmatrix_x4(Alf[slot][mt], ad + A_PLANE);
        }
#pragma unroll
        for (int q = 0; q < 4; q++) {
            uint32_t bd = C.b_base + (uint32_t)(q * 16 * TSTR + s * 32);
            ldmatrix_x4(Bhf[slot][q], bd);
            ldmatrix_x4(Blf[slot][q], bd + (OFF_BL - OFF_BH));
        }
    };

    loadfrag(0, 0);
#pragma unroll
    for (int s = 0; s < 8; s++) {
        const int cur = s & 1;
        if (s < 7) loadfrag(s + 1, cur ^ 1);
#pragma unroll
        for (int mt = 0; mt < 2; mt++)
#pragma unroll
            for (int nt = 0; nt < 8; nt++) {
                const uint32_t* bh = &Bhf[cur][nt >> 1][(nt & 1) * 2];
                const uint32_t* bl = &Blf[cur][nt >> 1][(nt & 1) * 2];
                mma16816(acc[mt][nt], Ahf[cur][mt], bh);   // hi*hi
                mma16816(acc[mt][nt], Alf[cur][mt], bh);   // lo*hi
                mma16816(acc[mt][nt], Ahf[cur][mt], bl);   // hi*lo
            }
    }

#pragma unroll
    for (int mt = 0; mt < 2; mt++) {
        int row0 = m0 + C.wm * 32 + mt * 16 + C.g;
#pragma unroll
        for (int nt = 0; nt < 8; nt++) {
            int col = C.wn * 64 + nt * 8 + C.tq * 2;
            float b0v = C.bs[col], b1v = C.bs[col + 1];
            int cc = C.isY ? col : (col - 128);
            if (row0 < NV) {
                float2 o = make_float2(acc[mt][nt][0] + b0v, acc[mt][nt][1] + b1v);
                *(float2*)(C.dbase + (size_t)row0 * 128 + cc) = o;
            }
            if (row0 + 8 < NV) {
                float2 o = make_float2(acc[mt][nt][2] + b0v, acc[mt][nt][3] + b1v);
                *(float2*)(C.dbase + (size_t)(row0 + 8) * 128 + cc) = o;
            }
        }
    }
}

// ---------------------------------------------------------------------------
// Persistent, pipelined tensor-core dual GEMM (split-bf16, 3xMMA, fp32-class):
//   Yout[m,0:128] = X @ W0^T + b0 ;  Nbuf[m,0:128] = X @ W1^T + b1
// Grid = #SM CTAs. Each CTA: load B (weights) ONCE, then loop over 64-row
// A-tiles with stride gridDim, double-buffered cp.async A prefetch.
// ---------------------------------------------------------------------------
__global__ __launch_bounds__(256, 1)
void gemm_dual_tc(const __nv_bfloat16* __restrict__ XH,
                  const __nv_bfloat16* __restrict__ XL,
                  const __nv_bfloat16* __restrict__ WH,
                  const __nv_bfloat16* __restrict__ WL,
                  const float* __restrict__ b0, const float* __restrict__ b1,
                  float* __restrict__ Yout, float* __restrict__ Nbuf)
{
    extern __shared__ char smem[];
    const uint32_t sb = smem_u32(smem);
    const int tid  = threadIdx.x;
    const int wid  = tid >> 5;
    const int lane = tid & 31;

    ((float*)(smem + OFF_BIAS))[tid] = (tid < 128) ? b0[tid] : b1[tid - 128];

#pragma unroll
    for (int i = 0; i < 16; i++) {
        int c = tid + i * 256;
        int n = c >> 4, kc = c & 15;
        uint32_t so = (uint32_t)(n * TSTR + kc * 16);
        const size_t go = ((size_t)n << 7) + kc * 8;
        cp16(sb + OFF_BH + so, WH + go);
        cp16(sb + OFF_BL + so, WL + go);
    }

    auto issueA = [&](int t, int buf) {
        const uint32_t abase = sb + (buf ? OFF_A1 : OFF_A0);
        char* abasep = smem + (buf ? OFF_A1 : OFF_A0);
        const int m0 = t * 64;
#pragma unroll
        for (int i = 0; i < 4; i++) {
            int c = tid + i * 256;
            int r = c >> 4, kc = c & 15;
            int grow = m0 + r;
            uint32_t so = (uint32_t)(r * TSTR + kc * 16);
            if (grow < NV) {
                const size_t go = ((size_t)grow << 7) + kc * 8;
                cp16(abase + so, XH + go);
                cp16(abase + A_PLANE + so, XL + go);
            } else {
                *(uint4*)(abasep + so) = make_uint4(0, 0, 0, 0);
                *(uint4*)(abasep + A_PLANE + so) = make_uint4(0, 0, 0, 0);
            }
        }
    };

    int t = blockIdx.x;
    if (t >= NT64) return;
    issueA(t, 0);
    asm volatile("cp.async.commit_group;");

    MmaCtx C;
    C.wm = wid & 1; C.wn = wid >> 1;
    C.a_roff = (uint32_t)((C.wm * 32 + (lane & 15)) * TSTR + ((lane >> 4) * 8) * 2);
    C.b_base = sb + OFF_BH +
               (uint32_t)((C.wn * 64 + (lane & 7) + ((lane >> 4) * 8)) * TSTR +
                          (((lane >> 3) & 1) * 8) * 2);
    C.g = lane >> 2; C.tq = lane & 3;
    C.isY = (C.wn < 2);
    C.dbase = C.isY ? Yout : Nbuf;
    C.bs = (const float*)(smem + OFF_BIAS);

    int p = 0;
    while (t < NT64) {
        const int tn = t + gridDim.x;
        if (tn < NT64) {
            issueA(tn, p ^ 1);
            asm volatile("cp.async.commit_group;");
            asm volatile("cp.async.wait_group 1;");
        } else {
            asm volatile("cp.async.wait_group 0;");
        }
        __syncthreads();
        mma_tile(C, sb + (p ? OFF_A1 : OFF_A0) + C.a_roff, t * 64, Yout, Nbuf);
        __syncthreads();
        t = tn;
        p ^= 1;
    }
}

// ---------------------------------------------------------------------------
// CSR build kernels (edges are static; built once per launch)
// ---------------------------------------------------------------------------
__global__ __launch_bounds__(256)
void deg_count(const int2* __restrict__ edges, int* __restrict__ deg)
{
    int t = blockIdx.x * blockDim.x + threadIdx.x;
    if (t >= NE) return;
    int2 e = edges[t];
    atomicAdd(&deg[e.x], 1);
    atomicAdd(&deg[e.y], 1);
}

__global__ __launch_bounds__(1024)
void scan1(const int* __restrict__ deg, int* __restrict__ incl, int* __restrict__ bsum)
{
    __shared__ int ws[32];
    int i = blockIdx.x * 1024 + threadIdx.x;
    int lane = threadIdx.x & 31, wid = threadIdx.x >> 5;
    int x = (i < NV) ? deg[i] : 0;
#pragma unroll
    for (int d = 1; d < 32; d <<= 1) {
        int t = __shfl_up_sync(0xffffffffu, x, d);
        if (lane >= d) x += t;
    }
    if (lane == 31) ws[wid] = x;
    __syncthreads();
    if (wid == 0) {
        int w = ws[lane];
#pragma unroll
        for (int d = 1; d < 32; d <<= 1) {
            int t = __shfl_up_sync(0xffffffffu, w, d);
            if (lane >= d) w += t;
        }
        ws[lane] = w;
    }
    __syncthreads();
    int off = (wid > 0) ? ws[wid - 1] : 0;
    int v = x + off;
    if (i < NV) incl[i] = v;
    if (threadIdx.x == 1023) bsum[blockIdx.x] = v;
}

__global__ void scan2(int* bsum)
{
    if (threadIdx.x == 0 && blockIdx.x == 0) {
        int acc = 0;
        for (int b = 0; b < NB_SCAN; b++) { int t = bsum[b]; bsum[b] = acc; acc += t; }
    }
}

__global__ __launch_bounds__(256)
void scan3(const int* __restrict__ incl, const int* __restrict__ deg,
           const int* __restrict__ bsum, int* __restrict__ indptr,
           int* __restrict__ cursor)
{
    int i = blockIdx.x * blockDim.x + threadIdx.x;
    if (i >= NV) return;
    int total = incl[i] + bsum[i >> 10];
    int ex = total - deg[i];
    indptr[i] = ex;
    cursor[i] = ex;
    if (i == NV - 1) indptr[NV] = total;
}

__global__ __launch_bounds__(256)
void fill_adj(const int2* __restrict__ edges, int* __restrict__ cursor,
              int* __restrict__ adj)
{
    int t = blockIdx.x * blockDim.x + threadIdx.x;
    if (t >= NE) return;
    int2 e = edges[t];
    int p = atomicAdd(&cursor[e.x], 1); adj[p] = e.y;
    int q = atomicAdd(&cursor[e.y], 1); adj[q] = e.x;
}

// ---------------------------------------------------------------------------
// Weight pre-split: all 13 layers' (W0|W1) fp32 -> bf16 hi/lo planes
// ---------------------------------------------------------------------------
__global__ __launch_bounds__(256)
void wsplit(const float* __restrict__ W0_1, const float* __restrict__ W1_1,
            const float* __restrict__ W0_h, const float* __restrict__ W1_h,
            __nv_bfloat16* __restrict__ WH, __nv_bfloat16* __restrict__ WL)
{
    int idx = blockIdx.x * blockDim.x + threadIdx.x;   // float4 units
    if (idx >= 13 * 256 * 32) return;
    int layer = idx / (256 * 32);
    int rem   = idx % (256 * 32);
    int row   = rem >> 5;
    int c4    = (rem & 31) * 4;
    const float* src;
    if (layer == 0)
        src = (row < 128) ? (W0_1 + (size_t)row * 128) : (W1_1 + (size_t)(row - 128) * 128);
    else
        src = (row < 128) ? (W0_h + (size_t)(layer - 1) * 16384 + (size_t)row * 128)
                          : (W1_h + (size_t)(layer - 1) * 16384 + (size_t)(row - 128) * 128);
    float4 v = *(const float4*)(src + c4);
    __nv_bfloat16 h0 = __float2bfloat16_rn(v.x), h1 = __float2bfloat16_rn(v.y);
    __nv_bfloat16 h2 = __float2bfloat16_rn(v.z), h3 = __float2bfloat16_rn(v.w);
    float l0 = v.x - __bfloat162float(h0), l1 = v.y - __bfloat162float(h1);
    float l2 = v.z - __bfloat162float(h2), l3 = v.w - __bfloat162float(h3);
    size_t o = ((size_t)(layer * 256 + row) << 7) + c4;
    *(uint2*)(WH + o) = make_uint2(pk(h0, h1), pk(h2, h3));
    *(uint2*)(WL + o) = make_uint2(pk(__float2bfloat16_rn(l0), __float2bfloat16_rn(l1)),
                                   pk(__float2bfloat16_rn(l2), __float2bfloat16_rn(l3)));
}

// features fp32 -> hi/lo planes (no relu)
__global__ __launch_bounds__(256)
void featsplit(const float4* __restrict__ X, __nv_bfloat16* __restrict__ AH,
               __nv_bfloat16* __restrict__ AL)
{
    int idx = blockIdx.x * blockDim.x + threadIdx.x;   // float4 units
    if (idx >= NV * 32) return;
    float4 v = X[idx];
    __nv_bfloat16 h0 = __float2bfloat16_rn(v.x), h1 = __float2bfloat16_rn(v.y);
    __nv_bfloat16 h2 = __float2bfloat16_rn(v.z), h3 = __float2bfloat16_rn(v.w);
    float l0 = v.x - __bfloat162float(h0), l1 = v.y - __bfloat162float(h1);
    float l2 = v.z - __bfloat162float(h2), l3 = v.w - __bfloat162float(h3);
    *(uint2*)(AH + (size_t)idx * 4) = make_uint2(pk(h0, h1), pk(h2, h3));
    *(uint2*)(AL + (size_t)idx * 4) =
        make_uint2(pk(__float2bfloat16_rn(l0), __float2bfloat16_rn(l1)),
                   pk(__float2bfloat16_rn(l2), __float2bfloat16_rn(l3)));
}

// ---------------------------------------------------------------------------
// CSR gather-aggregate: x = relu(Y[v] + sum_{j in adj(v)} N[j]); emit hi/lo
// planes. Warp per vertex, lane = one float4. 4-way index batch -> MLP=4.
// ---------------------------------------------------------------------------
__global__ __launch_bounds__(256)
void agg_csr(const float4* __restrict__ Y, const float4* __restrict__ Nb,
             const int* __restrict__ indptr, const int* __restrict__ adj,
             __nv_bfloat16* __restrict__ AH, __nv_bfloat16* __restrict__ AL)
{
    int w = (blockIdx.x * blockDim.x + threadIdx.x) >> 5;
    int lane = threadIdx.x & 31;
    if (w >= NV) return;
    float4 acc = ldcs4(Y + (size_t)w * 32 + lane);   // streaming read, evict-first
    const int s = indptr[w], e = indptr[w + 1];
    int k = s;
    for (; k + 4 <= e; k += 4) {
        int j0 = __ldg(adj + k), j1 = __ldg(adj + k + 1);
        int j2 = __ldg(adj + k + 2), j3 = __ldg(adj + k + 3);
        float4 n0 = Nb[(size_t)j0 * 32 + lane];
        float4 n1 = Nb[(size_t)j1 * 32 + lane];
        float4 n2 = Nb[(size_t)j2 * 32 + lane];
        float4 n3 = Nb[(size_t)j3 * 32 + lane];
        acc.x += (n0.x + n1.x) + (n2.x + n3.x);
        acc.y += (n0.y + n1.y) + (n2.y + n3.y);
        acc.z += (n0.z + n1.z) + (n2.z + n3.z);
        acc.w += (n0.w + n1.w) + (n2.w + n3.w);
    }
    if (k + 2 <= e) {
        int j0 = __ldg(adj + k), j1 = __ldg(adj + k + 1);
        float4 n0 = Nb[(size_t)j0 * 32 + lane];
        float4 n1 = Nb[(size_t)j1 * 32 + lane];
        acc.x += n0.x + n1.x; acc.y += n0.y + n1.y;
        acc.z += n0.z + n1.z; acc.w += n0.w + n1.w;
        k += 2;
    }
    if (k < e) {
        int j0 = __ldg(adj + k);
        float4 n0 = Nb[(size_t)j0 * 32 + lane];
        acc.x += n0.x; acc.y += n0.y; acc.z += n0.z; acc.w += n0.w;
    }
    acc.x = fmaxf(acc.x, 0.f); acc.y = fmaxf(acc.y, 0.f);
    acc.z = fmaxf(acc.z, 0.f); acc.w = fmaxf(acc.w, 0.f);
    __nv_bfloat16 h0 = __float2bfloat16_rn(acc.x), h1 = __float2bfloat16_rn(acc.y);
    __nv_bfloat16 h2 = __float2bfloat16_rn(acc.z), h3 = __float2bfloat16_rn(acc.w);
    float l0 = acc.x - __bfloat162float(h0), l1 = acc.y - __bfloat162float(h1);
    float l2 = acc.z - __bfloat162float(h2), l3 = acc.w - __bfloat162float(h3);
    size_t o = ((size_t)w << 7) + lane * 4;
    *(uint2*)(AH + o) = make_uint2(pk(h0, h1), pk(h2, h3));
    *(uint2*)(AL + o) = make_uint2(pk(__float2bfloat16_rn(l0), __float2bfloat16_rn(l1)),
                                   pk(__float2bfloat16_rn(l2), __float2bfloat16_rn(l3)));
}

// ---------------------------------------------------------------------------
// Final layer (+ fused aux emit): z = (Rh+Rl) + (Ah+Al);
//   y = z@W0l^T + b0l; n = z@W1l^T + b1l; aux = Ah+Al
// ---------------------------------------------------------------------------
__global__ __launch_bounds__(256)
void final_gemm(const __nv_bfloat16* __restrict__ Rh, const __nv_bfloat16* __restrict__ Rl,
                const __nv_bfloat16* __restrict__ Ahp, const __nv_bfloat16* __restrict__ Alp,
                const float* __restrict__ W0, const float* __restrict__ b0,
                const float* __restrict__ W1, const float* __restrict__ b1,
                float* __restrict__ Yout /*NV*3*/, float* __restrict__ Nl /*NV*3*/,
                float* __restrict__ Aux /*NV*128*/)
{
    __shared__ float w[6][128];
    int tid = threadIdx.x;
    for (int i = tid; i < 384; i += blockDim.x) {
        w[i / 128][i % 128]     = W0[i];
        w[3 + i / 128][i % 128] = W1[i];
    }
    __syncthreads();

    int row  = blockIdx.x * (blockDim.x >> 5) + (tid >> 5);
    int lane = tid & 31;
    if (row >= NV) return;

    size_t o = ((size_t)row << 7) + lane * 4;
    uint2 rh = *(const uint2*)(Rh + o), rl = *(const uint2*)(Rl + o);
    uint2 ah = *(const uint2*)(Ahp + o), al = *(const uint2*)(Alp + o);
    float2 a0 = up2(rh.x), a1 = up2(rh.y), b0f = up2(rl.x), b1f = up2(rl.y);
    float2 c0 = up2(ah.x), c1 = up2(ah.y), d0 = up2(al.x), d1 = up2(al.y);
    float4 ax = make_float4(c0.x + d0.x, c0.y + d0.y, c1.x + d1.x, c1.y + d1.y);
    *(float4*)(Aux + o) = ax;
    float4 z;
    z.x = (a0.x + b0f.x) + ax.x;
    z.y = (a0.y + b0f.y) + ax.y;
    z.z = (a1.x + b1f.x) + ax.z;
    z.w = (a1.y + b1f.y) + ax.w;

    float s[6];
#pragma unroll
    for (int oo = 0; oo < 6; oo++) {
        float4 wv = ((const float4*)w[oo])[lane];
        s[oo] = z.x * wv.x + z.y * wv.y + z.z * wv.z + z.w * wv.w;
    }
#pragma unroll
    for (int off = 16; off > 0; off >>= 1)
#pragma unroll
        for (int oo = 0; oo < 6; oo++)
            s[oo] += __shfl_down_sync(0xffffffffu, s[oo], off);

    if (lane == 0) {
#pragma unroll
        for (int oo = 0; oo < 3; oo++) {
            Yout[(size_t)row * 3 + oo] = s[oo] + b0[oo];
            Nl[(size_t)row * 3 + oo]   = s[3 + oo] + b1[oo];
        }
    }
}

// Final scatter over D_OUT=3
__global__ __launch_bounds__(256)
void scatter3(const float* __restrict__ Nl, const int2* __restrict__ edges,
              float* __restrict__ Out)
{
    int t = blockIdx.x * blockDim.x + threadIdx.x;
    if (t >= NE) return;
    int2 e = edges[t];
#pragma unroll
    for (int o = 0; o < 3; o++) {
        atomicAdd(Out + (size_t)e.x * 3 + o, Nl[(size_t)e.y * 3 + o]);
        atomicAdd(Out + (size_t)e.y * 3 + o, Nl[(size_t)e.x * 3 + o]);
    }
}

// ---------------------------------------------------------------------------
extern "C" void kernel_launch(void* const* d_in, const int* in_sizes, int n_in,
                              void* d_out, int out_size)
{
    const float* features = (const float*)d_in[0];
    const int2*  edges    = (const int2*)d_in[1];
    const float* W0_1 = (const float*)d_in[2];
    const float* b0_1 = (const float*)d_in[3];
    const float* W1_1 = (const float*)d_in[4];
    const float* b1_1 = (const float*)d_in[5];
    const float* W0_h = (const float*)d_in[6];
    const float* b0_h = (const float*)d_in[7];
    const float* W1_h = (const float*)d_in[8];
    const float* b1_h = (const float*)d_in[9];
    const float* W0_l = (const float*)d_in[10];
    const float* b0_l = (const float*)d_in[11];
    const float* W1_l = (const float*)d_in[12];
    const float* b1_l = (const float*)d_in[13];
    float* out = (float*)d_out;   // [vertices NV*3 | auxiliary NV*128]

    float *Y, *N, *NL;
    __nv_bfloat16 *Ah, *Al, *Rh, *Rl, *WH, *WL;
    int *deg, *incl, *bsum, *indptr, *cursor, *adj;
    cudaGetSymbolAddress((void**)&Y,  g_Y);
    cudaGetSymbolAddress((void**)&N,  g_N);
    cudaGetSymbolAddress((void**)&NL, g_NL);
    cudaGetSymbolAddress((void**)&Ah, g_Ah);
    cudaGetSymbolAddress((void**)&Al, g_Al);
    cudaGetSymbolAddress((void**)&Rh, g_Rh);
    cudaGetSymbolAddress((void**)&Rl, g_Rl);
    cudaGetSymbolAddress((void**)&WH, g_WH);
    cudaGetSymbolAddress((void**)&WL, g_WL);
    cudaGetSymbolAddress((void**)&deg,    g_deg);
    cudaGetSymbolAddress((void**)&incl,   g_incl);
    cudaGetSymbolAddress((void**)&bsum,   g_bsum);
    cudaGetSymbolAddress((void**)&indptr, g_indptr);
    cudaGetSymbolAddress((void**)&cursor, g_cursor);
    cudaGetSymbolAddress((void**)&adj,    g_adj);

    cudaFuncSetAttribute(gemm_dual_tc,
                         cudaFuncAttributeMaxDynamicSharedMemorySize, SMEM_TOTAL);

    int dev = 0, sms = 148;
    cudaGetDevice(&dev);
    cudaDeviceGetAttribute(&sms, cudaDevAttrMultiProcessorCount, dev);
    const int gemmBlocks = (sms < NT64) ? sms : NT64;   // persistent: 1 CTA/SM
    const int aggBlocks  = (NV * 32 + 255) / 256;       // warp per vertex
    const int edgeBlocks = (NE + 255) / 256;

    // ---- CSR build (edges static; rebuilt each call for determinism) ----
    cudaMemsetAsync(deg, 0, NV * sizeof(int));
    deg_count<<<edgeBlocks, 256>>>(edges, deg);
    scan1<<<NB_SCAN, 1024>>>(deg, incl, bsum);
    scan2<<<1, 32>>>(bsum);
    scan3<<<(NV + 255) / 256, 256>>>(incl, deg, bsum, indptr, cursor);
    fill_adj<<<edgeBlocks, 256>>>(edges, cursor, adj);

    // ---- one-time conversions ----
    wsplit<<<(13 * 256 * 32 + 255) / 256, 256>>>(W0_1, W1_1, W0_h, W1_h, WH, WL);
    featsplit<<<(NV * 32 + 255) / 256, 256>>>((const float4*)features, Ah, Al);

    // ---- layer 1 (in -> hidden) ----
    gemm_dual_tc<<<gemmBlocks, 256, SMEM_TOTAL>>>(Ah, Al, WH, WL, b0_1, b1_1, Y, N);
    agg_csr<<<aggBlocks, 256>>>((const float4*)Y, (const float4*)N, indptr, adj, Rh, Rl);

    // ---- 12 hidden layers ----
    const __nv_bfloat16* ih = Rh;
    const __nv_bfloat16* il = Rl;
    for (int l = 0; l < LHID; l++) {
        gemm_dual_tc<<<gemmBlocks, 256, SMEM_TOTAL>>>(
            ih, il, WH + (size_t)(1 + l) * 256 * 128, WL + (size_t)(1 + l) * 256 * 128,
            b0_h + l * DH, b1_h + l * DH, Y, N);
        agg_csr<<<aggBlocks, 256>>>((const float4*)Y, (const float4*)N, indptr, adj, Ah, Al);
        ih = Ah; il = Al;
    }
    // Ah/Al now hold relu(last hidden output) planes.

    // ---- final layer (+aux): z = relu(residual) + relu(x_last) ----
    final_gemm<<<(NV + 7) / 8, 256>>>(Rh, Rl, Ah, Al, W0_l, b0_l, W1_l, b1_l,
                                      out, NL, out + (size_t)NV * 3);
    scatter3<<<edgeBlocks, 256>>>(NL, edges, out);
}